// round 3
// baseline (speedup 1.0000x reference)
#include <cuda_runtime.h>
#include <cstdint>

#define H 2048
#define W 2048
#define HW (H*W)
#define NSTR (HW/4)
#define NSEG 10
#define NB 2048            // histogram bins over [0, 1/32)
#define HIST_SCALE 65536.0f
#define HIST_CAP 0.03125f

__device__ unsigned int g_dmin_bits;
__device__ unsigned int g_dmax_bits;
__device__ unsigned int g_hist_cnt[NSEG*NB];
__device__ float        g_hist_sum[NSEG*NB];
__device__ double       g_csum[NSEG*3];
__device__ double       g_ncnt[NSEG];
__device__ float4       g_Dseg[NSEG+1];
__device__ unsigned char g_segmap[HW];
__device__ float        g_dmap[HW];

static __device__ __forceinline__ float f_inf() { return __int_as_float(0x7f800000); }

// ---------------- K0: zero scratch ----------------
__global__ void k0_init() {
    int i = blockIdx.x * blockDim.x + threadIdx.x;
    if (i < NSEG*NB) { g_hist_cnt[i] = 0u; g_hist_sum[i] = 0.0f; }
    if (i < NSEG*3)  g_csum[i] = 0.0;
    if (i < NSEG)    g_ncnt[i] = 0.0;
    if (i == 0) { g_dmin_bits = 0x7f800000u; g_dmax_bits = 0u; }
}

// ---------------- K1: depth min/max ----------------
__global__ void __launch_bounds__(256) k1_minmax(const float* __restrict__ depth) {
    float lmin = f_inf(), lmax = -f_inf();
    for (int t = blockIdx.x * blockDim.x + threadIdx.x; t < NSTR; t += gridDim.x * blockDim.x) {
        float4 d = reinterpret_cast<const float4*>(depth)[t];
        lmin = fminf(lmin, fminf(fminf(d.x, d.y), fminf(d.z, d.w)));
        lmax = fmaxf(lmax, fmaxf(fmaxf(d.x, d.y), fmaxf(d.z, d.w)));
    }
    #pragma unroll
    for (int o = 16; o > 0; o >>= 1) {
        lmin = fminf(lmin, __shfl_down_sync(0xffffffffu, lmin, o));
        lmax = fmaxf(lmax, __shfl_down_sync(0xffffffffu, lmax, o));
    }
    __shared__ float smin[8], smax[8];
    int w = threadIdx.x >> 5, l = threadIdx.x & 31;
    if (l == 0) { smin[w] = lmin; smax[w] = lmax; }
    __syncthreads();
    if (threadIdx.x == 0) {
        float bm = smin[0], bM = smax[0];
        #pragma unroll
        for (int i = 1; i < 8; i++) { bm = fminf(bm, smin[i]); bM = fmaxf(bM, smax[i]); }
        atomicMin(&g_dmin_bits, __float_as_uint(bm));  // depth >= 0: uint order == float order
        atomicMax(&g_dmax_bits, __float_as_uint(bM));
    }
}

// ---------------- K2: per-pixel stats, segmap, dmap ----------------
__global__ void __launch_bounds__(256) k2_stats(const float* __restrict__ img,
                                                const float* __restrict__ depth,
                                                const float* __restrict__ mu0p,
                                                const float* __restrict__ mu1p,
                                                const float* __restrict__ mu2p) {
    const float dmin = __uint_as_float(g_dmin_bits);
    const float dmax = __uint_as_float(g_dmax_bits);
    const float step = (dmax - dmin) / 10.0f;
    float bins[11];
    #pragma unroll
    for (int i = 0; i <= 10; i++) bins[i] = __fadd_rn(dmin, __fmul_rn((float)i, step));
    bins[10] = dmax;  // linspace endpoint set exactly

    const float mu0 = mu0p[0], mu1 = mu1p[0], mu2 = mu2p[0];

    float an[NSEG], ar[NSEG], ag[NSEG], ab[NSEG];
    #pragma unroll
    for (int i = 0; i < NSEG; i++) { an[i] = 0.f; ar[i] = 0.f; ag[i] = 0.f; ab[i] = 0.f; }

    for (int t = blockIdx.x * blockDim.x + threadIdx.x; t < NSTR; t += gridDim.x * blockDim.x) {
        float4 dd = reinterpret_cast<const float4*>(depth)[t];
        float4 rr = reinterpret_cast<const float4*>(img)[t];
        float4 gg = reinterpret_cast<const float4*>(img)[t + NSTR];
        float4 bb = reinterpret_cast<const float4*>(img)[t + 2*NSTR];
        float dv[4] = {dd.x, dd.y, dd.z, dd.w};
        float rv[4] = {rr.x, rr.y, rr.z, rr.w};
        float gv[4] = {gg.x, gg.y, gg.z, gg.w};
        float bv[4] = {bb.x, bb.y, bb.z, bb.w};
        unsigned char sm[4];
        float dm[4];
        #pragma unroll
        for (int j = 0; j < 4; j++) {
            float d = dv[j], r = rv[j], g = gv[j], b = bv[j];
            int s = 0;
            #pragma unroll
            for (int i = 1; i <= 10; i++) s += (d >= bins[i]) ? 1 : 0;  // s==10 -> no segment
            sm[j] = (unsigned char)s;
            dm[j] = (mu0 + mu1 * fmaxf(g, b)) + mu2 * r;
            float m = fminf(r, fminf(g, b));
            if (s < NSEG) {
                #pragma unroll
                for (int i = 0; i < NSEG; i++) {
                    if (s == i) { an[i] += 1.0f; ar[i] += r; ag[i] += g; ab[i] += b; }
                }
                if (m < HIST_CAP) {
                    int bin = (int)(m * HIST_SCALE);
                    atomicAdd(&g_hist_cnt[s*NB + bin], 1u);
                    atomicAdd(&g_hist_sum[s*NB + bin], m);
                }
            }
        }
        reinterpret_cast<uchar4*>(g_segmap)[t] = make_uchar4(sm[0], sm[1], sm[2], sm[3]);
        reinterpret_cast<float4*>(g_dmap)[t]   = make_float4(dm[0], dm[1], dm[2], dm[3]);
    }

    // warp-reduce each accumulator; lane 0 does double atomics (exact integer counts)
    int lane = threadIdx.x & 31;
    #pragma unroll
    for (int i = 0; i < NSEG; i++) {
        float vn = an[i], vr = ar[i], vg = ag[i], vb = ab[i];
        #pragma unroll
        for (int o = 16; o > 0; o >>= 1) {
            vn += __shfl_down_sync(0xffffffffu, vn, o);
            vr += __shfl_down_sync(0xffffffffu, vr, o);
            vg += __shfl_down_sync(0xffffffffu, vg, o);
            vb += __shfl_down_sync(0xffffffffu, vb, o);
        }
        if (lane == 0) {
            atomicAdd(&g_ncnt[i], (double)vn);
            atomicAdd(&g_csum[i*3+0], (double)vr);
            atomicAdd(&g_csum[i*3+1], (double)vg);
            atomicAdd(&g_csum[i*3+2], (double)vb);
        }
    }
}

// ---------------- K3: finalize (B_c via histogram selection, D_seg) ----------------
__global__ void k3_finalize() {
    int warp = threadIdx.x >> 5;
    int lane = threadIdx.x & 31;
    if (warp < NSEG) {
        int s = warp;
        long long n = (long long)(g_ncnt[s] + 0.5);
        unsigned int k = (unsigned int)(n / 100);

        // each lane owns 64 contiguous bins
        int base = s*NB + lane*64;
        unsigned int ccnt = 0; double csum = 0.0;
        for (int i = 0; i < 64; i++) { ccnt += g_hist_cnt[base+i]; csum += (double)g_hist_sum[base+i]; }
        unsigned int inc = ccnt; double incs = csum;
        #pragma unroll
        for (int o = 1; o < 32; o <<= 1) {
            unsigned int tc = __shfl_up_sync(0xffffffffu, inc, o);
            double ts = __shfl_up_sync(0xffffffffu, incs, o);
            if (lane >= o) { inc += tc; incs += ts; }
        }
        unsigned int excl = inc - ccnt;
        double excls = incs - csum;

        bool mine = (k > 0) && (excl < k) && (inc >= k);
        float bc_val = 0.0f;
        if (mine) {
            unsigned int need = k - excl;
            double sum_below = excls;
            unsigned int crun = 0;
            for (int i = 0; i < 64; i++) {
                unsigned int bcnt = g_hist_cnt[base+i];
                float bsum = g_hist_sum[base+i];
                if (crun + bcnt >= need) {
                    unsigned int rem = need - crun;
                    double avg = (bcnt > 0) ? ((double)bsum / (double)bcnt) : 0.0;
                    sum_below += avg * (double)rem;
                    break;
                }
                crun += bcnt;
                sum_below += (double)bsum;
            }
            bc_val = (float)(sum_below / (double)k);
        }
        unsigned int msk = __ballot_sync(0xffffffffu, mine);
        int src = msk ? (__ffs(msk) - 1) : 0;
        float Bc = __shfl_sync(0xffffffffu, bc_val, src);
        if (msk == 0u) Bc = 0.0f;

        if (lane == 0) {
            double nn = (double)n;
            float mr = (float)(g_csum[s*3+0] / nn);
            float mg = (float)(g_csum[s*3+1] / nn);
            float mb = (float)(g_csum[s*3+2] / nn);
            g_Dseg[s] = make_float4(mr - Bc, mg - Bc, mb - Bc, 0.0f);
        }
    }
    if (threadIdx.x == 0) g_Dseg[NSEG] = make_float4(0.f, 0.f, 0.f, 0.f);
}

// ---------------- K4: 3x3 smoothing + output ----------------
__global__ void __launch_bounds__(256) k4_output(const float* __restrict__ depth,
                                                 float* __restrict__ out) {
    __shared__ float4 sD[NSEG+1];
    if (threadIdx.x < NSEG+1) sD[threadIdx.x] = g_Dseg[threadIdx.x];
    __syncthreads();

    int t = blockIdx.x * blockDim.x + threadIdx.x;   // strip of 4 px
    if (t >= NSTR) return;
    int y  = t >> 9;            // / (W/4)
    int xb = (t & 511) << 2;

    float dep[3][6];
    int   sg[3][6];
    #pragma unroll
    for (int r = 0; r < 3; r++) {
        int yy = y + r - 1;
        bool rok = (yy >= 0) && (yy < H);
        #pragma unroll
        for (int c = 0; c < 6; c++) {
            int xx = xb + c - 1;
            bool ok = rok && (xx >= 0) && (xx < W);
            int idx = yy * W + xx;
            dep[r][c] = ok ? __ldg(depth + idx) : f_inf();
            sg[r][c]  = ok ? (int)g_segmap[idx] : NSEG;
        }
    }
    float4 dm = reinterpret_cast<const float4*>(g_dmap)[t];
    float dmv[4] = {dm.x, dm.y, dm.z, dm.w};
    float orr[4], org[4], orb[4];
    #pragma unroll
    for (int j = 0; j < 4; j++) {
        float dc = dep[1][j+1];
        float nr = 0.f, ng = 0.f, nb = 0.f, cnt = 0.f;
        #pragma unroll
        for (int r = 0; r < 3; r++) {
            #pragma unroll
            for (int c = 0; c < 3; c++) {
                float nd = dep[r][j+c];
                if (fabsf(nd - dc) < 1.0f) {
                    float4 dvv = sD[sg[r][j+c]];
                    nr += dvv.x; ng += dvv.y; nb += dvv.z; cnt += 1.0f;
                }
            }
        }
        float4 Dc = sD[sg[1][j+1]];
        float ax = 0.5f * Dc.x + 0.5f * (nr / cnt);
        float ay = 0.5f * Dc.y + 0.5f * (ng / cnt);
        float az = 0.5f * Dc.z + 0.5f * (nb / cnt);
        float dv = dmv[j];
        orr[j] = 2.0f * ax * dv;
        org[j] = 2.0f * ay * dv;
        orb[j] = 2.0f * az * dv;
    }
    reinterpret_cast<float4*>(out)[t]          = make_float4(orr[0], orr[1], orr[2], orr[3]);
    reinterpret_cast<float4*>(out)[t +   NSTR] = make_float4(org[0], org[1], org[2], org[3]);
    reinterpret_cast<float4*>(out)[t + 2*NSTR] = make_float4(orb[0], orb[1], orb[2], orb[3]);
}

extern "C" void kernel_launch(void* const* d_in, const int* in_sizes, int n_in,
                              void* d_out, int out_size) {
    const float* img   = (const float*)d_in[0];
    const float* depth = (const float*)d_in[1];
    const float* mu0   = (const float*)d_in[2];
    const float* mu1   = (const float*)d_in[3];
    const float* mu2   = (const float*)d_in[4];
    float* out = (float*)d_out;

    k0_init<<<(NSEG*NB + 255) / 256, 256>>>();
    k1_minmax<<<592, 256>>>(depth);
    k2_stats<<<592, 256>>>(img, depth, mu0, mu1, mu2);
    k3_finalize<<<1, 320>>>();
    k4_output<<<NSTR / 256, 256>>>(depth, out);
}

// round 4
// speedup vs baseline: 1.8884x; 1.8884x over previous
#include <cuda_runtime.h>
#include <cstdint>

#define H 2048
#define W 2048
#define HW (H*W)
#define NSTR (HW/4)
#define NSEG 10
#define NB 2048            // histogram bins over [0, 1/32)
#define HIST_SCALE 65536.0f
#define HIST_CAP 0.03125f

__device__ unsigned int g_dmin_bits;
__device__ unsigned int g_dmax_bits;
__device__ unsigned int g_hist_cnt[NSEG*NB];
__device__ float        g_hist_sum[NSEG*NB];
__device__ double       g_csum[NSEG*3];
__device__ double       g_ncnt[NSEG];
__device__ float4       g_Dseg[NSEG+1];
__device__ unsigned char g_segmap[HW];
__device__ float        g_dmap[HW];

static __device__ __forceinline__ float f_inf() { return __int_as_float(0x7f800000); }

static __device__ __forceinline__ float2 unpk(unsigned long long v) {
    float2 r; asm("mov.b64 {%0,%1}, %2;" : "=f"(r.x), "=f"(r.y) : "l"(v)); return r;
}
static __device__ __forceinline__ unsigned long long pk(float a, float b) {
    unsigned long long r; asm("mov.b64 %0, {%1,%2};" : "=l"(r) : "f"(a), "f"(b)); return r;
}
#define ADDX2(acc, val) asm("add.rn.f32x2 %0, %1, %2;" : "=l"(acc) : "l"(acc), "l"(val))

// ---------------- K0: zero scratch ----------------
__global__ void k0_init() {
    int i = blockIdx.x * blockDim.x + threadIdx.x;
    if (i < NSEG*NB) { g_hist_cnt[i] = 0u; g_hist_sum[i] = 0.0f; }
    if (i < NSEG*3)  g_csum[i] = 0.0;
    if (i < NSEG)    g_ncnt[i] = 0.0;
    if (i == 0) { g_dmin_bits = 0x7f800000u; g_dmax_bits = 0u; }
}

// ---------------- K1: depth min/max ----------------
__global__ void __launch_bounds__(256) k1_minmax(const float* __restrict__ depth) {
    float lmin = f_inf(), lmax = -f_inf();
    for (int t = blockIdx.x * blockDim.x + threadIdx.x; t < NSTR; t += gridDim.x * blockDim.x) {
        float4 d = reinterpret_cast<const float4*>(depth)[t];
        lmin = fminf(lmin, fminf(fminf(d.x, d.y), fminf(d.z, d.w)));
        lmax = fmaxf(lmax, fmaxf(fmaxf(d.x, d.y), fmaxf(d.z, d.w)));
    }
    #pragma unroll
    for (int o = 16; o > 0; o >>= 1) {
        lmin = fminf(lmin, __shfl_down_sync(0xffffffffu, lmin, o));
        lmax = fmaxf(lmax, __shfl_down_sync(0xffffffffu, lmax, o));
    }
    __shared__ float smin[8], smax[8];
    int w = threadIdx.x >> 5, l = threadIdx.x & 31;
    if (l == 0) { smin[w] = lmin; smax[w] = lmax; }
    __syncthreads();
    if (threadIdx.x == 0) {
        float bm = smin[0], bM = smax[0];
        #pragma unroll
        for (int i = 1; i < 8; i++) { bm = fminf(bm, smin[i]); bM = fmaxf(bM, smax[i]); }
        atomicMin(&g_dmin_bits, __float_as_uint(bm));  // depth >= 0: uint order == float order
        atomicMax(&g_dmax_bits, __float_as_uint(bM));
    }
}

// ---------------- K2: per-pixel stats, segmap, dmap ----------------
__global__ void __launch_bounds__(256) k2_stats(const float* __restrict__ img,
                                                const float* __restrict__ depth,
                                                const float* __restrict__ mu0p,
                                                const float* __restrict__ mu1p,
                                                const float* __restrict__ mu2p) {
    // warp-replicated per-seg accumulators: [warp][seg*4 + {n,r,g,b}]
    __shared__ float s_acc[8][NSEG*4];
    for (int i = threadIdx.x; i < 8*NSEG*4; i += blockDim.x)
        ((float*)s_acc)[i] = 0.0f;
    __syncthreads();

    const float dmin = __uint_as_float(g_dmin_bits);
    const float dmax = __uint_as_float(g_dmax_bits);
    const float inv_step = 10.0f / (dmax - dmin);
    const float mu0 = mu0p[0], mu1 = mu1p[0], mu2 = mu2p[0];
    const int w = threadIdx.x >> 5;
    float* acc = s_acc[w];

    for (int t = blockIdx.x * blockDim.x + threadIdx.x; t < NSTR; t += gridDim.x * blockDim.x) {
        float4 dd = reinterpret_cast<const float4*>(depth)[t];
        float4 rr = reinterpret_cast<const float4*>(img)[t];
        float4 gg = reinterpret_cast<const float4*>(img)[t + NSTR];
        float4 bb = reinterpret_cast<const float4*>(img)[t + 2*NSTR];
        float dv[4] = {dd.x, dd.y, dd.z, dd.w};
        float rv[4] = {rr.x, rr.y, rr.z, rr.w};
        float gv[4] = {gg.x, gg.y, gg.z, gg.w};
        float bv[4] = {bb.x, bb.y, bb.z, bb.w};
        unsigned char sm[4];
        float dm[4];
        #pragma unroll
        for (int j = 0; j < 4; j++) {
            float d = dv[j], r = rv[j], g = gv[j], b = bv[j];
            int s = (int)((d - dmin) * inv_step);
            s = min(s, 9);
            if (d >= dmax) s = NSEG;         // exact-max pixel(s) excluded, as in reference
            sm[j] = (unsigned char)s;
            dm[j] = fmaf(mu2, r, fmaf(mu1, fmaxf(g, b), mu0));
            if (s < NSEG) {
                float* a4 = acc + s*4;
                atomicAdd(a4 + 0, 1.0f);
                atomicAdd(a4 + 1, r);
                atomicAdd(a4 + 2, g);
                atomicAdd(a4 + 3, b);
                float m = fminf(r, fminf(g, b));
                if (m < HIST_CAP) {
                    int bin = (int)(m * HIST_SCALE);
                    atomicAdd(&g_hist_cnt[s*NB + bin], 1u);
                    atomicAdd(&g_hist_sum[s*NB + bin], m);
                }
            }
        }
        reinterpret_cast<uchar4*>(g_segmap)[t] = make_uchar4(sm[0], sm[1], sm[2], sm[3]);
        reinterpret_cast<float4*>(g_dmap)[t]   = make_float4(dm[0], dm[1], dm[2], dm[3]);
    }

    __syncthreads();
    if (threadIdx.x < NSEG*4) {
        float v = 0.0f;
        #pragma unroll
        for (int i = 0; i < 8; i++) v += s_acc[i][threadIdx.x];
        int s = threadIdx.x >> 2, c = threadIdx.x & 3;
        if (c == 0) atomicAdd(&g_ncnt[s], (double)v);
        else        atomicAdd(&g_csum[s*3 + c - 1], (double)v);
    }
}

// ---------------- K3: finalize (parallel histogram selection, D_seg) ----------------
// grid = NSEG blocks, 256 threads; each thread owns 8 contiguous bins.
__global__ void __launch_bounds__(256) k3_finalize() {
    const int s = blockIdx.x;
    const int tid = threadIdx.x;
    const int lane = tid & 31, w = tid >> 5;
    const int base = s*NB + tid*8;

    uint4  ca = *reinterpret_cast<const uint4*>(&g_hist_cnt[base]);
    uint4  cb = *reinterpret_cast<const uint4*>(&g_hist_cnt[base+4]);
    float4 sa = *reinterpret_cast<const float4*>(&g_hist_sum[base]);
    float4 sb = *reinterpret_cast<const float4*>(&g_hist_sum[base+4]);

    unsigned int cc[8] = {ca.x, ca.y, ca.z, ca.w, cb.x, cb.y, cb.z, cb.w};
    float        ss[8] = {sa.x, sa.y, sa.z, sa.w, sb.x, sb.y, sb.z, sb.w};

    unsigned int ccnt = 0; double csum = 0.0;
    #pragma unroll
    for (int i = 0; i < 8; i++) { ccnt += cc[i]; csum += (double)ss[i]; }

    // inclusive warp scan
    unsigned int inc = ccnt; double incs = csum;
    #pragma unroll
    for (int o = 1; o < 32; o <<= 1) {
        unsigned int tc = __shfl_up_sync(0xffffffffu, inc, o);
        double ts = __shfl_up_sync(0xffffffffu, incs, o);
        if (lane >= o) { inc += tc; incs += ts; }
    }
    __shared__ unsigned int wc[8];
    __shared__ double ws[8];
    __shared__ float sBc;
    if (lane == 31) { wc[w] = inc; ws[w] = incs; }
    if (tid == 0) sBc = 0.0f;
    __syncthreads();
    unsigned int coff = 0; double soff = 0.0;
    #pragma unroll
    for (int i = 0; i < 8; i++) if (i < w) { coff += wc[i]; soff += ws[i]; }
    inc += coff; incs += soff;
    unsigned int excl = inc - ccnt;
    double excls = incs - csum;

    long long n = (long long)(g_ncnt[s] + 0.5);
    unsigned int k = (unsigned int)(n / 100);

    if (k > 0 && excl < k && inc >= k) {   // exactly one thread
        unsigned int need = k - excl;
        double sum_below = excls;
        unsigned int crun = 0;
        #pragma unroll
        for (int i = 0; i < 8; i++) {
            if (crun + cc[i] >= need) {
                unsigned int rem = need - crun;
                double avg = (cc[i] > 0) ? ((double)ss[i] / (double)cc[i]) : 0.0;
                sum_below += avg * (double)rem;
                break;
            }
            crun += cc[i];
            sum_below += (double)ss[i];
        }
        sBc = (float)(sum_below / (double)k);
    }
    __syncthreads();
    if (tid == 0) {
        double nn = (double)n;
        float Bc = sBc;
        float mr = (float)(g_csum[s*3+0] / nn);
        float mg = (float)(g_csum[s*3+1] / nn);
        float mb = (float)(g_csum[s*3+2] / nn);
        g_Dseg[s] = make_float4(mr - Bc, mg - Bc, mb - Bc, 0.0f);
    }
    if (s == 0 && tid == 32) g_Dseg[NSEG] = make_float4(0.f, 0.f, 0.f, 0.f);
}

// ---------------- K4: 3x3 smoothing + output ----------------
__global__ void __launch_bounds__(256) k4_output(const float* __restrict__ depth,
                                                 float* __restrict__ out) {
    // packed LUT: [i] = { (Dx,Dy), (Dz, 1.0) } for segs 0..10; [11] = all zeros (invalid)
    __shared__ ulonglong2 sLut[12];
    if (threadIdx.x < 12) {
        if (threadIdx.x < 11) {
            float4 v = g_Dseg[threadIdx.x];
            sLut[threadIdx.x].x = pk(v.x, v.y);
            sLut[threadIdx.x].y = pk(v.z, 1.0f);
        } else {
            sLut[11].x = 0ull; sLut[11].y = 0ull;
        }
    }
    __syncthreads();

    int t = blockIdx.x * blockDim.x + threadIdx.x;   // strip of 4 px
    if (t >= NSTR) return;
    int y  = t >> 9;            // / (W/4)
    int xb = (t & 511) << 2;
    const float INFV = f_inf();

    float dep[3][6];
    int   sg[3][6];
    #pragma unroll
    for (int r = 0; r < 3; r++) {
        int yy = y + r - 1;
        if ((unsigned)yy < (unsigned)H) {
            const float* dp = depth + yy * W + xb;
            float4 c4 = __ldg(reinterpret_cast<const float4*>(dp));
            dep[r][1] = c4.x; dep[r][2] = c4.y; dep[r][3] = c4.z; dep[r][4] = c4.w;
            dep[r][0] = (xb > 0)       ? __ldg(dp - 1) : INFV;
            dep[r][5] = (xb + 4 < W)   ? __ldg(dp + 4) : INFV;
            const unsigned char* sp = g_segmap + yy * W + xb;
            uchar4 s4 = *reinterpret_cast<const uchar4*>(sp);
            sg[r][1] = s4.x; sg[r][2] = s4.y; sg[r][3] = s4.z; sg[r][4] = s4.w;
            sg[r][0] = (xb > 0)     ? (int)sp[-1] : 11;
            sg[r][5] = (xb + 4 < W) ? (int)sp[4]  : 11;
        } else {
            #pragma unroll
            for (int c = 0; c < 6; c++) { dep[r][c] = INFV; sg[r][c] = 11; }
        }
    }

    float4 dmq = reinterpret_cast<const float4*>(g_dmap)[t];
    float dmv[4] = {dmq.x, dmq.y, dmq.z, dmq.w};
    float orr[4], org[4], orb[4];
    #pragma unroll
    for (int j = 0; j < 4; j++) {
        float dc = dep[1][j+1];
        ulonglong2 v0 = sLut[sg[1][j+1]];          // center: always valid, counts 1
        unsigned long long acc0 = v0.x, acc1 = v0.y;
        #pragma unroll
        for (int r = 0; r < 3; r++) {
            #pragma unroll
            for (int c = 0; c < 3; c++) {
                if (r == 1 && c == 1) continue;
                bool ok = fabsf(dep[r][j+c] - dc) < 1.0f;
                int idx = ok ? sg[r][j+c] : 11;
                ulonglong2 v = sLut[idx];
                ADDX2(acc0, v.x);
                ADDX2(acc1, v.y);
            }
        }
        float2 rg  = unpk(acc0);
        float2 bc2 = unpk(acc1);
        float2 Drg = unpk(v0.x);
        float2 Dbc = unpk(v0.y);
        float rcn; asm("rcp.approx.f32 %0, %1;" : "=f"(rcn) : "f"(bc2.y));
        float dv = dmv[j];
        // J = 2*(0.5*D + 0.5*num/cnt)*d = (D + num*rcn)*d
        orr[j] = fmaf(rg.x,  rcn, Drg.x) * dv;
        org[j] = fmaf(rg.y,  rcn, Drg.y) * dv;
        orb[j] = fmaf(bc2.x, rcn, Dbc.x) * dv;
    }
    reinterpret_cast<float4*>(out)[t]          = make_float4(orr[0], orr[1], orr[2], orr[3]);
    reinterpret_cast<float4*>(out)[t +   NSTR] = make_float4(org[0], org[1], org[2], org[3]);
    reinterpret_cast<float4*>(out)[t + 2*NSTR] = make_float4(orb[0], orb[1], orb[2], orb[3]);
}

extern "C" void kernel_launch(void* const* d_in, const int* in_sizes, int n_in,
                              void* d_out, int out_size) {
    const float* img   = (const float*)d_in[0];
    const float* depth = (const float*)d_in[1];
    const float* mu0   = (const float*)d_in[2];
    const float* mu1   = (const float*)d_in[3];
    const float* mu2   = (const float*)d_in[4];
    float* out = (float*)d_out;

    k0_init<<<(NSEG*NB + 255) / 256, 256>>>();
    k1_minmax<<<608, 256>>>(depth);
    k2_stats<<<608, 256>>>(img, depth, mu0, mu1, mu2);
    k3_finalize<<<NSEG, 256>>>();
    k4_output<<<NSTR / 256, 256>>>(depth, out);
}